// round 1
// baseline (speedup 1.0000x reference)
#include <cuda_runtime.h>
#include <math.h>

#define N_NODES 100000
#define FEAT    256
#define HEADS   8
#define HEAD_DIM 32
#define E_EDGES 800000

// ---------------- scratch (no cudaMalloc allowed) ----------------
__device__ float g_q[(size_t)N_NODES * FEAT];
__device__ float g_k[(size_t)N_NODES * FEAT];
__device__ float g_v[(size_t)N_NODES * FEAT];
__device__ float g_acc[(size_t)N_NODES * FEAT];
__device__ float g_attn[(size_t)E_EDGES * HEADS];
__device__ float g_m[(size_t)N_NODES * HEADS];
__device__ float g_s[(size_t)N_NODES * HEADS];

// ---------------- helpers ----------------
__device__ __forceinline__ void atomicMaxFloat(float* addr, float value) {
    // monotonic bit trick: works for mixed-sign floats, init with -inf
    if (value >= 0.0f) {
        atomicMax((int*)addr, __float_as_int(value));
    } else {
        atomicMin((unsigned int*)addr, __float_as_uint(value));
    }
}

// ---------------- init: m=-inf, s=0, acc=0 ----------------
__global__ void init_kernel(float* m, float* s, float* acc, int nmh, int nacc) {
    int i = blockIdx.x * blockDim.x + threadIdx.x;
    int stride = gridDim.x * blockDim.x;
    float ninf = __int_as_float(0xFF800000);
    for (int j = i; j < nacc; j += stride) acc[j] = 0.0f;
    for (int j = i; j < nmh; j += stride) { m[j] = ninf; s[j] = 0.0f; }
}

// ---------------- GEMM: C[M,256] = (A ./ rowdiv) @ W^T * outScale ----------------
// A row-major [M,256], W row-major [256,256] (nn.Linear weight), C row-major.
// rowdiv (nullable): per (row, head) divisor, [M*HEADS]; guard div==0 -> 0.
#define BM 64
#define BN 64
#define BKK 32

__global__ void gemm_xwT_kernel(const float* __restrict__ A,
                                const float* __restrict__ W,
                                float* __restrict__ C,
                                int M, float outScale,
                                const float* __restrict__ rowdiv) {
    __shared__ float As[BKK][BM + 1];
    __shared__ float Bs[BKK][BN + 1];

    int tid = threadIdx.x;          // 256 threads
    int tx = tid & 15;              // 0..15
    int ty = tid >> 4;              // 0..15
    int row0 = blockIdx.y * BM;
    int col0 = blockIdx.x * BN;

    float acc[4][4];
#pragma unroll
    for (int i = 0; i < 4; i++)
#pragma unroll
        for (int j = 0; j < 4; j++) acc[i][j] = 0.0f;

    for (int k0 = 0; k0 < FEAT; k0 += BKK) {
        // A tile: 64 rows x 32 k  (2048 elems / 256 threads = 8 each)
#pragma unroll
        for (int i = 0; i < 8; i++) {
            int idx = tid + i * 256;
            int m  = idx >> 5;
            int kk = idx & 31;
            int gm = row0 + m;
            float val = 0.0f;
            if (gm < M) {
                val = A[(size_t)gm * FEAT + k0 + kk];
                if (rowdiv) {
                    float dv = rowdiv[gm * HEADS + ((k0 + kk) >> 5)];
                    val = (dv > 0.0f) ? (val / dv) : 0.0f;
                }
            }
            As[kk][m] = val;
        }
        // B tile: Bs[kk][j] = W[(col0+j)*256 + k0+kk]
#pragma unroll
        for (int i = 0; i < 8; i++) {
            int idx = tid + i * 256;
            int j  = idx >> 5;
            int kk = idx & 31;
            Bs[kk][j] = W[(size_t)(col0 + j) * FEAT + k0 + kk];
        }
        __syncthreads();

#pragma unroll
        for (int kk = 0; kk < BKK; kk++) {
            float a[4], b[4];
#pragma unroll
            for (int i = 0; i < 4; i++) a[i] = As[kk][ty * 4 + i];
#pragma unroll
            for (int j = 0; j < 4; j++) b[j] = Bs[kk][tx * 4 + j];
#pragma unroll
            for (int i = 0; i < 4; i++)
#pragma unroll
                for (int j = 0; j < 4; j++)
                    acc[i][j] = fmaf(a[i], b[j], acc[i][j]);
        }
        __syncthreads();
    }

#pragma unroll
    for (int i = 0; i < 4; i++) {
        int gm = row0 + ty * 4 + i;
        if (gm < M) {
#pragma unroll
            for (int j = 0; j < 4; j++) {
                C[(size_t)gm * FEAT + col0 + tx * 4 + j] = acc[i][j] * outScale;
            }
        }
    }
}

// ---------------- edge pass 1: logits + segment max ----------------
// one warp per edge; lane covers d=lane of each head.
__global__ void edge_attn_kernel(const float* __restrict__ q,
                                 const float* __restrict__ k,
                                 const float* __restrict__ bias,
                                 const int* __restrict__ src,
                                 const int* __restrict__ dst,
                                 float* __restrict__ attn,
                                 float* __restrict__ m, int E) {
    int e = (int)((blockIdx.x * (size_t)blockDim.x + threadIdx.x) >> 5);
    int lane = threadIdx.x & 31;
    if (e >= E) return;
    int sn = src[e], dn = dst[e];
    const float* kp = k + (size_t)sn * FEAT;
    const float* qp = q + (size_t)dn * FEAT;

    float sum[HEADS];
#pragma unroll
    for (int h = 0; h < HEADS; h++)
        sum[h] = kp[h * HEAD_DIM + lane] * qp[h * HEAD_DIM + lane];
#pragma unroll
    for (int h = 0; h < HEADS; h++) {
#pragma unroll
        for (int off = 16; off > 0; off >>= 1)
            sum[h] += __shfl_xor_sync(0xffffffffu, sum[h], off);
    }
    if (lane == 0) {
#pragma unroll
        for (int h = 0; h < HEADS; h++) {
            float a = sum[h] + bias[(size_t)e * HEADS + h];
            attn[(size_t)e * HEADS + h] = a;
            atomicMaxFloat(&m[dn * HEADS + h], a);
        }
    }
}

// ---------------- edge pass 2: exp, segment sum, scatter-add a*v[src] ----------------
__global__ void edge_accum_kernel(const float* __restrict__ v,
                                  const float* __restrict__ attn,
                                  const float* __restrict__ m,
                                  float* __restrict__ s_sum,
                                  float* __restrict__ acc,
                                  const int* __restrict__ src,
                                  const int* __restrict__ dst, int E) {
    int e = (int)((blockIdx.x * (size_t)blockDim.x + threadIdx.x) >> 5);
    int lane = threadIdx.x & 31;
    if (e >= E) return;
    int sn = src[e], dn = dst[e];

    float a = 0.0f;
    if (lane < HEADS) {
        a = expf(attn[(size_t)e * HEADS + lane] - m[dn * HEADS + lane]);
        atomicAdd(&s_sum[dn * HEADS + lane], a);
    }
    const float* vp = v + (size_t)sn * FEAT;
    float* ap = acc + (size_t)dn * FEAT;
#pragma unroll
    for (int h = 0; h < HEADS; h++) {
        float ah = __shfl_sync(0xffffffffu, a, h);
        atomicAdd(&ap[h * HEAD_DIM + lane], ah * vp[h * HEAD_DIM + lane]);
    }
}

// ---------------- launch ----------------
extern "C" void kernel_launch(void* const* d_in, const int* in_sizes, int n_in,
                              void* d_out, int out_size) {
    const float* nfeat = (const float*)d_in[0];
    const float* attn_bias = (const float*)d_in[1];
    const float* Wq = (const float*)d_in[2];
    const float* Wk = (const float*)d_in[3];
    const float* Wv = (const float*)d_in[4];
    const float* Wo = (const float*)d_in[5];
    const int* src = (const int*)d_in[6];
    const int* dst = (const int*)d_in[7];
    float* out = (float*)d_out;

    int N = in_sizes[0] / FEAT;
    int E = in_sizes[6];

    float *q, *k, *v, *acc, *attn, *m, *s;
    cudaGetSymbolAddress((void**)&q, g_q);
    cudaGetSymbolAddress((void**)&k, g_k);
    cudaGetSymbolAddress((void**)&v, g_v);
    cudaGetSymbolAddress((void**)&acc, g_acc);
    cudaGetSymbolAddress((void**)&attn, g_attn);
    cudaGetSymbolAddress((void**)&m, g_m);
    cudaGetSymbolAddress((void**)&s, g_s);

    // init m/s/acc
    init_kernel<<<4096, 256>>>(m, s, acc, N * HEADS, N * FEAT);

    // projections
    dim3 ggrid(FEAT / BN, (N + BM - 1) / BM);
    const float invScaling = 5.656854249492381f;  // sqrt(HEAD_DIM): reference DIVIDES q by scaling
    gemm_xwT_kernel<<<ggrid, 256>>>(nfeat, Wq, q, N, invScaling, nullptr);
    gemm_xwT_kernel<<<ggrid, 256>>>(nfeat, Wk, k, N, 1.0f, nullptr);
    gemm_xwT_kernel<<<ggrid, 256>>>(nfeat, Wv, v, N, 1.0f, nullptr);

    // edge passes (1 warp / edge)
    int eblocks = (E * 32 + 255) / 256;
    edge_attn_kernel<<<eblocks, 256>>>(q, k, attn_bias, src, dst, attn, m, E);
    edge_accum_kernel<<<eblocks, 256>>>(v, attn, m, s, acc, src, dst, E);

    // final projection with fold-in normalization by s (guard s==0 -> 0)
    gemm_xwT_kernel<<<ggrid, 256>>>(acc, Wo, out, N, 1.0f, s);
}

// round 2
// speedup vs baseline: 1.3513x; 1.3513x over previous
#include <cuda_runtime.h>
#include <math.h>

#define N_NODES 100000
#define FEAT    256
#define HEADS   8
#define HEAD_DIM 32
#define E_EDGES 800000

// ---------------- scratch (no cudaMalloc allowed) ----------------
__device__ float g_q[(size_t)N_NODES * FEAT];
__device__ float g_k[(size_t)N_NODES * FEAT];
__device__ float g_v[(size_t)N_NODES * FEAT];
__device__ float g_acc[(size_t)N_NODES * FEAT];
__device__ float g_attn[(size_t)E_EDGES * HEADS];
__device__ float g_m[(size_t)N_NODES * HEADS];
__device__ float g_s[(size_t)N_NODES * HEADS];

// ---------------- helpers ----------------
__device__ __forceinline__ void atomicMaxFloat(float* addr, float value) {
    if (value >= 0.0f) {
        atomicMax((int*)addr, __float_as_int(value));
    } else {
        atomicMin((unsigned int*)addr, __float_as_uint(value));
    }
}

// ---------------- init: m=-inf, s=0, acc=0 ----------------
__global__ void init_kernel(float* m, float* s, float* acc, int nmh, int nacc) {
    int i = blockIdx.x * blockDim.x + threadIdx.x;
    int stride = gridDim.x * blockDim.x;
    float ninf = __int_as_float(0xFF800000);
    for (int j = i; j < nacc; j += stride) acc[j] = 0.0f;
    for (int j = i; j < nmh; j += stride) { m[j] = ninf; s[j] = 0.0f; }
}

// ---------------- GEMM v2: C[M,256] = (A ./ rowdiv) @ W^T * outScale ----------------
// 128x128 block tile, BK=16, 256 threads, 8x8 per thread, double-buffered smem,
// float4 global loads + float4 LDS. A row-major [M,256], W row-major [256,256].
#define BM 128
#define BN 128
#define BK 16
#define NKT (FEAT / BK)   // 16 k-tiles

__global__ __launch_bounds__(256) void gemm_xwT_kernel(
        const float* __restrict__ A,
        const float* __restrict__ W,
        float* __restrict__ C,
        int M, float outScale,
        const float* __restrict__ rowdiv) {
    __shared__ float As[2][BK][BM];
    __shared__ float Bs[2][BK][BN];

    const int tid = threadIdx.x;        // 256 threads
    const int tx = tid & 15;            // 0..15 -> 8 cols each
    const int ty = tid >> 4;            // 0..15 -> 8 rows each
    const int row0 = blockIdx.y * BM;
    const int col0 = blockIdx.x * BN;

    // load mapping: 512 float4s per tile side; thread handles f = tid*2 + {0,1}
    // f -> row = f>>2 (0..127), kq = f&3 (which float4 in the 16-wide k strip)
    const int lrow = tid >> 1;                 // rows this thread loads (same for i=0,1)
    const int lkq0 = (tid & 1) * 2;            // kq = lkq0 + i

    float racc[8][8];
#pragma unroll
    for (int i = 0; i < 8; i++)
#pragma unroll
        for (int j = 0; j < 8; j++) racc[i][j] = 0.0f;

    // ---- prologue: load tile 0 into buffer 0 ----
    {
        const int gm = row0 + lrow;
#pragma unroll
        for (int i = 0; i < 2; i++) {
            int kq = lkq0 + i;
            float4 va = make_float4(0.f, 0.f, 0.f, 0.f);
            if (gm < M) {
                va = *(const float4*)&A[(size_t)gm * FEAT + kq * 4];
                if (rowdiv) {
                    // head index of k = (kq*4 + j) >> 5; within one float4 all same head
                    float dv = rowdiv[gm * HEADS + ((kq * 4) >> 5)];
                    float r = (dv > 0.0f) ? (1.0f / dv) : 0.0f;
                    va.x *= r; va.y *= r; va.z *= r; va.w *= r;
                }
            }
            As[0][kq * 4 + 0][lrow] = va.x;
            As[0][kq * 4 + 1][lrow] = va.y;
            As[0][kq * 4 + 2][lrow] = va.z;
            As[0][kq * 4 + 3][lrow] = va.w;

            float4 vb = *(const float4*)&W[(size_t)(col0 + lrow) * FEAT + kq * 4];
            Bs[0][kq * 4 + 0][lrow] = vb.x;
            Bs[0][kq * 4 + 1][lrow] = vb.y;
            Bs[0][kq * 4 + 2][lrow] = vb.z;
            Bs[0][kq * 4 + 3][lrow] = vb.w;
        }
    }
    __syncthreads();

    for (int t = 0; t < NKT; t++) {
        const int buf = t & 1;
        float4 pa[2], pb[2];
        const bool pf = (t + 1 < NKT);
        if (pf) {
            const int k0 = (t + 1) * BK;
            const int gm = row0 + lrow;
#pragma unroll
            for (int i = 0; i < 2; i++) {
                int kq = lkq0 + i;
                pa[i] = make_float4(0.f, 0.f, 0.f, 0.f);
                if (gm < M) {
                    pa[i] = *(const float4*)&A[(size_t)gm * FEAT + k0 + kq * 4];
                    if (rowdiv) {
                        float dv = rowdiv[gm * HEADS + ((k0 + kq * 4) >> 5)];
                        float r = (dv > 0.0f) ? (1.0f / dv) : 0.0f;
                        pa[i].x *= r; pa[i].y *= r; pa[i].z *= r; pa[i].w *= r;
                    }
                }
                pb[i] = *(const float4*)&W[(size_t)(col0 + lrow) * FEAT + k0 + kq * 4];
            }
        }

        // ---- compute on buf ----
#pragma unroll
        for (int kk = 0; kk < BK; kk++) {
            float4 a0 = *(const float4*)&As[buf][kk][ty * 8];
            float4 a1 = *(const float4*)&As[buf][kk][ty * 8 + 4];
            float4 b0 = *(const float4*)&Bs[buf][kk][tx * 8];
            float4 b1 = *(const float4*)&Bs[buf][kk][tx * 8 + 4];
            float a[8] = {a0.x, a0.y, a0.z, a0.w, a1.x, a1.y, a1.z, a1.w};
            float b[8] = {b0.x, b0.y, b0.z, b0.w, b1.x, b1.y, b1.z, b1.w};
#pragma unroll
            for (int i = 0; i < 8; i++)
#pragma unroll
                for (int j = 0; j < 8; j++)
                    racc[i][j] = fmaf(a[i], b[j], racc[i][j]);
        }

        if (pf) {
            const int nbuf = buf ^ 1;
#pragma unroll
            for (int i = 0; i < 2; i++) {
                int kq = lkq0 + i;
                As[nbuf][kq * 4 + 0][lrow] = pa[i].x;
                As[nbuf][kq * 4 + 1][lrow] = pa[i].y;
                As[nbuf][kq * 4 + 2][lrow] = pa[i].z;
                As[nbuf][kq * 4 + 3][lrow] = pa[i].w;
                Bs[nbuf][kq * 4 + 0][lrow] = pb[i].x;
                Bs[nbuf][kq * 4 + 1][lrow] = pb[i].y;
                Bs[nbuf][kq * 4 + 2][lrow] = pb[i].z;
                Bs[nbuf][kq * 4 + 3][lrow] = pb[i].w;
            }
            __syncthreads();
        }
    }

    // ---- epilogue: float4 stores ----
#pragma unroll
    for (int i = 0; i < 8; i++) {
        int gm = row0 + ty * 8 + i;
        if (gm < M) {
            float4 o0, o1;
            o0.x = racc[i][0] * outScale; o0.y = racc[i][1] * outScale;
            o0.z = racc[i][2] * outScale; o0.w = racc[i][3] * outScale;
            o1.x = racc[i][4] * outScale; o1.y = racc[i][5] * outScale;
            o1.z = racc[i][6] * outScale; o1.w = racc[i][7] * outScale;
            *(float4*)&C[(size_t)gm * FEAT + col0 + tx * 8] = o0;
            *(float4*)&C[(size_t)gm * FEAT + col0 + tx * 8 + 4] = o1;
        }
    }
}

// ---------------- edge pass 1: logits + segment max ----------------
__global__ void edge_attn_kernel(const float* __restrict__ q,
                                 const float* __restrict__ k,
                                 const float* __restrict__ bias,
                                 const int* __restrict__ src,
                                 const int* __restrict__ dst,
                                 float* __restrict__ attn,
                                 float* __restrict__ m, int E) {
    int e = (int)((blockIdx.x * (size_t)blockDim.x + threadIdx.x) >> 5);
    int lane = threadIdx.x & 31;
    if (e >= E) return;
    int sn = src[e], dn = dst[e];
    const float* kp = k + (size_t)sn * FEAT;
    const float* qp = q + (size_t)dn * FEAT;

    float sum[HEADS];
#pragma unroll
    for (int h = 0; h < HEADS; h++)
        sum[h] = kp[h * HEAD_DIM + lane] * qp[h * HEAD_DIM + lane];
#pragma unroll
    for (int h = 0; h < HEADS; h++) {
#pragma unroll
        for (int off = 16; off > 0; off >>= 1)
            sum[h] += __shfl_xor_sync(0xffffffffu, sum[h], off);
    }
    // lanes 0..7 each handle one head (reduction result valid on all lanes)
    if (lane < HEADS) {
        float a = sum[lane] + bias[(size_t)e * HEADS + lane];
        attn[(size_t)e * HEADS + lane] = a;
        atomicMaxFloat(&m[dn * HEADS + lane], a);
    }
}

// ---------------- edge pass 2: exp, segment sum, scatter-add a*v[src] ----------------
__global__ void edge_accum_kernel(const float* __restrict__ v,
                                  const float* __restrict__ attn,
                                  const float* __restrict__ m,
                                  float* __restrict__ s_sum,
                                  float* __restrict__ acc,
                                  const int* __restrict__ src,
                                  const int* __restrict__ dst, int E) {
    int e = (int)((blockIdx.x * (size_t)blockDim.x + threadIdx.x) >> 5);
    int lane = threadIdx.x & 31;
    if (e >= E) return;
    int sn = src[e], dn = dst[e];

    float a = 0.0f;
    if (lane < HEADS) {
        a = expf(attn[(size_t)e * HEADS + lane] - m[dn * HEADS + lane]);
        atomicAdd(&s_sum[dn * HEADS + lane], a);
    }
    const float* vp = v + (size_t)sn * FEAT;
    float* ap = acc + (size_t)dn * FEAT;
#pragma unroll
    for (int h = 0; h < HEADS; h++) {
        float ah = __shfl_sync(0xffffffffu, a, h);
        atomicAdd(&ap[h * HEAD_DIM + lane], ah * vp[h * HEAD_DIM + lane]);
    }
}

// ---------------- launch ----------------
extern "C" void kernel_launch(void* const* d_in, const int* in_sizes, int n_in,
                              void* d_out, int out_size) {
    const float* nfeat = (const float*)d_in[0];
    const float* attn_bias = (const float*)d_in[1];
    const float* Wq = (const float*)d_in[2];
    const float* Wk = (const float*)d_in[3];
    const float* Wv = (const float*)d_in[4];
    const float* Wo = (const float*)d_in[5];
    const int* src = (const int*)d_in[6];
    const int* dst = (const int*)d_in[7];
    float* out = (float*)d_out;

    int N = in_sizes[0] / FEAT;
    int E = in_sizes[6];

    float *q, *k, *v, *acc, *attn, *m, *s;
    cudaGetSymbolAddress((void**)&q, g_q);
    cudaGetSymbolAddress((void**)&k, g_k);
    cudaGetSymbolAddress((void**)&v, g_v);
    cudaGetSymbolAddress((void**)&acc, g_acc);
    cudaGetSymbolAddress((void**)&attn, g_attn);
    cudaGetSymbolAddress((void**)&m, g_m);
    cudaGetSymbolAddress((void**)&s, g_s);

    // init m/s/acc
    init_kernel<<<4096, 256>>>(m, s, acc, N * HEADS, N * FEAT);

    // projections
    dim3 ggrid(FEAT / BN, (N + BM - 1) / BM);
    const float invScaling = 5.656854249492381f;  // sqrt(HEAD_DIM): reference DIVIDES q by scaling
    gemm_xwT_kernel<<<ggrid, 256>>>(nfeat, Wq, q, N, invScaling, nullptr);
    gemm_xwT_kernel<<<ggrid, 256>>>(nfeat, Wk, k, N, 1.0f, nullptr);
    gemm_xwT_kernel<<<ggrid, 256>>>(nfeat, Wv, v, N, 1.0f, nullptr);

    // edge passes (1 warp / edge)
    int eblocks = (E * 32 + 255) / 256;
    edge_attn_kernel<<<eblocks, 256>>>(q, k, attn_bias, src, dst, attn, m, E);
    edge_accum_kernel<<<eblocks, 256>>>(v, attn, m, s, acc, src, dst, E);

    // final projection with fold-in normalization by s (guard s==0 -> 0)
    gemm_xwT_kernel<<<ggrid, 256>>>(acc, Wo, out, N, 1.0f, s);
}

// round 4
// speedup vs baseline: 2.4773x; 1.8333x over previous
#include <cuda_runtime.h>
#include <cuda_bf16.h>
#include <math.h>
#include <stdint.h>

#define N_NODES 100000
#define FEAT    256
#define HEADS   8
#define HEAD_DIM 32
#define E_EDGES 800000

// ---------------- scratch (no cudaMalloc allowed) ----------------
__device__ float g_q[(size_t)N_NODES * FEAT];
__device__ float g_k[(size_t)N_NODES * FEAT];
__device__ float g_v[(size_t)N_NODES * FEAT];
__device__ float g_acc[(size_t)N_NODES * FEAT];
__device__ float g_attn[(size_t)E_EDGES * HEADS];
__device__ float g_m[(size_t)N_NODES * HEADS];
__device__ float g_s[(size_t)N_NODES * HEADS];
// bf16 hi/lo split inputs: [row][0..255]=hi, [row][256..511]=lo
__device__ __nv_bfloat16 g_a2[(size_t)N_NODES * 512];
__device__ __nv_bfloat16 g_acc2[(size_t)N_NODES * 512];
// W' = [Whi | Wlo | Whi], [256 rows][768 cols] bf16, per weight matrix
__device__ __nv_bfloat16 g_w2[4][(size_t)256 * 768];

// ================= PTX helpers (all non-'a' baseline features) =================
__device__ __forceinline__ uint32_t smem_to_u32(const void* p) {
    uint32_t a;
    asm("{ .reg .u64 t; cvta.to.shared.u64 t, %1; cvt.u32.u64 %0, t; }" : "=r"(a) : "l"(p));
    return a;
}

#define LDSM_X4(r0, r1, r2, r3, addr) \
    asm volatile("ldmatrix.sync.aligned.m8n8.x4.shared.b16 {%0,%1,%2,%3}, [%4];" \
        : "=r"(r0), "=r"(r1), "=r"(r2), "=r"(r3) : "r"(addr))

#define MMA_16816(c, a0, a1, a2, a3, b0, b1) \
    asm volatile("mma.sync.aligned.m16n8k16.row.col.f32.bf16.bf16.f32 " \
        "{%0,%1,%2,%3}, {%4,%5,%6,%7}, {%8,%9}, {%0,%1,%2,%3};" \
        : "+f"((c)[0]), "+f"((c)[1]), "+f"((c)[2]), "+f"((c)[3]) \
        : "r"(a0), "r"(a1), "r"(a2), "r"(a3), "r"(b0), "r"(b1))

__device__ __forceinline__ void cp_async16(uint32_t dst, const void* src, uint32_t src_size) {
    asm volatile("cp.async.cg.shared.global [%0], [%1], 16, %2;"
        :: "r"(dst), "l"(src), "r"(src_size) : "memory");
}
#define CP_ASYNC_COMMIT() asm volatile("cp.async.commit_group;" ::: "memory")
#define CP_ASYNC_WAIT_ALL() asm volatile("cp.async.wait_group 0;" ::: "memory")

// ---------------- helpers ----------------
__device__ __forceinline__ void atomicMaxFloat(float* addr, float value) {
    if (value >= 0.0f) atomicMax((int*)addr, __float_as_int(value));
    else atomicMin((unsigned int*)addr, __float_as_uint(value));
}

// ---------------- init: m=-inf, s=0, acc=0 ----------------
__global__ void init_kernel(float* m, float* s, float* acc, int nmh, int nacc) {
    int i = blockIdx.x * blockDim.x + threadIdx.x;
    int stride = gridDim.x * blockDim.x;
    float ninf = __int_as_float(0xFF800000);
    for (int j = i; j < nacc; j += stride) acc[j] = 0.0f;
    for (int j = i; j < nmh; j += stride) { m[j] = ninf; s[j] = 0.0f; }
}

// ---------------- fp32 -> bf16 hi/lo split (nodes / acc) ----------------
__global__ void conv_split_kernel(const float* __restrict__ X,
                                  __nv_bfloat16* __restrict__ Y,
                                  const float* __restrict__ sdiv,  // nullable per (row, head) divisor
                                  int rows) {
    int i = blockIdx.x * blockDim.x + threadIdx.x;   // one per float4: rows*64
    int tot = rows * 64;
    if (i >= tot) return;
    int row = i >> 6, qq = i & 63;
    float4 x = ((const float4*)X)[i];
    if (sdiv) {
        float dv = sdiv[row * HEADS + (qq >> 3)];    // 4 cols share one head
        float r = (dv > 0.0f) ? (1.0f / dv) : 0.0f;
        x.x *= r; x.y *= r; x.z *= r; x.w *= r;
    }
    __nv_bfloat16 h0 = __float2bfloat16(x.x), h1 = __float2bfloat16(x.y);
    __nv_bfloat16 h2 = __float2bfloat16(x.z), h3 = __float2bfloat16(x.w);
    __nv_bfloat16 l0 = __float2bfloat16(x.x - __bfloat162float(h0));
    __nv_bfloat16 l1 = __float2bfloat16(x.y - __bfloat162float(h1));
    __nv_bfloat16 l2 = __float2bfloat16(x.z - __bfloat162float(h2));
    __nv_bfloat16 l3 = __float2bfloat16(x.w - __bfloat162float(h3));
    uint32_t hA = ((uint32_t)__bfloat16_as_ushort(h1) << 16) | __bfloat16_as_ushort(h0);
    uint32_t hB = ((uint32_t)__bfloat16_as_ushort(h3) << 16) | __bfloat16_as_ushort(h2);
    uint32_t lA = ((uint32_t)__bfloat16_as_ushort(l1) << 16) | __bfloat16_as_ushort(l0);
    uint32_t lB = ((uint32_t)__bfloat16_as_ushort(l3) << 16) | __bfloat16_as_ushort(l2);
    size_t base = (size_t)row * 512 + qq * 4;
    *(uint2*)(Y + base)       = make_uint2(hA, hB);
    *(uint2*)(Y + base + 256) = make_uint2(lA, lB);
}

// ---------------- W -> W' = [Whi | Wlo | Whi], [256][768] bf16 ----------------
__global__ void conv_w_kernel(const float* __restrict__ W, __nv_bfloat16* __restrict__ W2) {
    int i = blockIdx.x * blockDim.x + threadIdx.x;   // 256*768
    if (i >= 256 * 768) return;
    int n = i / 768, kc = i % 768;
    int sk = (kc < 256) ? kc : ((kc < 512) ? kc - 256 : kc - 512);
    float w = W[n * 256 + sk];
    __nv_bfloat16 hi = __float2bfloat16(w);
    __nv_bfloat16 res;
    if (kc < 256 || kc >= 512) res = hi;
    else res = __float2bfloat16(w - __bfloat162float(hi));
    W2[(size_t)n * 768 + kc] = res;
}

// ---------------- HMMA GEMM: C[M,256] = A2split @ W2'^T * outScale ----------------
// A2: [M][512] bf16 (hi|lo). W2: [256][768] bf16. K=768 in 12 chunks of 64.
// Block tile 128(M) x 128(N), BK=64, 8 warps (warp tile 32x64), cp.async 2-stage.
#define NCHUNK 12
#define ROWB   144                 // padded smem row stride in bytes (72 bf16)
#define ATILE  (128 * ROWB)        // 18432 B
#define STAGE  (2 * ATILE)         // A + B per stage = 36864 B
#define GSMEM_BYTES (2 * STAGE)    // 73728 B

__global__ __launch_bounds__(256, 2) void gemm_mma_kernel(
        const __nv_bfloat16* __restrict__ A2,
        const __nv_bfloat16* __restrict__ W2,
        float* __restrict__ C,
        int M, float outScale) {
    extern __shared__ __align__(16) char smem[];
    const uint32_t sbase = smem_to_u32(smem);

    const int tid = threadIdx.x;
    const int lane = tid & 31;
    const int wid = tid >> 5;
    const int warp_m = wid & 3;          // 0..3 -> M offset 32*warp_m
    const int warp_n = wid >> 2;         // 0..1 -> N offset 64*warp_n
    const int row0 = blockIdx.y * 128;
    const int col0 = blockIdx.x * 128;

    // ---- global->smem load mapping (uint4 granules) ----
    const int lq = tid & 7;              // which 16B granule within a 128B row
    const int lr0 = tid >> 3;            // base row (stride 32 per iteration)

    // ---- ldmatrix per-lane address components (bytes) ----
    const uint32_t a_off = (uint32_t)((lane & 15) * ROWB + ((lane & 16) ? 16 : 0));
    const uint32_t b_off = (uint32_t)(((lane & 7) + ((lane & 16) ? 8 : 0)) * ROWB +
                                      ((lane & 8) ? 16 : 0));

    float cfr[2][8][4];
#pragma unroll
    for (int mi = 0; mi < 2; mi++)
#pragma unroll
        for (int ni = 0; ni < 8; ni++)
#pragma unroll
            for (int j = 0; j < 4; j++) cfr[mi][ni][j] = 0.0f;

    // ---- issue loads for chunk c into stage buffer ----
    auto issue_loads = [&](int c, int stage_idx) {
        const int srcoff = ((c < 8) ? 0 : 256) + (c & 3) * 64;   // A2 bf16 col offset
        const uint32_t sa = sbase + stage_idx * STAGE;
        const uint32_t sb = sa + ATILE;
#pragma unroll
        for (int it = 0; it < 4; it++) {
            int r = lr0 + it * 32;
            int gr = row0 + r;
            uint32_t ok = (gr < M) ? 16u : 0u;
            int grc = (gr < M) ? gr : 0;
            cp_async16(sa + r * ROWB + lq * 16,
                       A2 + (size_t)grc * 512 + srcoff + lq * 8, ok);
            cp_async16(sb + r * ROWB + lq * 16,
                       W2 + (size_t)(col0 + r) * 768 + c * 64 + lq * 8, 16u);
        }
        CP_ASYNC_COMMIT();
    };

    issue_loads(0, 0);
    CP_ASYNC_WAIT_ALL();
    __syncthreads();

    for (int c = 0; c < NCHUNK; c++) {
        if (c + 1 < NCHUNK) issue_loads(c + 1, (c + 1) & 1);

        const uint32_t sa = sbase + (c & 1) * STAGE + (warp_m * 32) * ROWB + a_off;
        const uint32_t sb = sbase + (c & 1) * STAGE + ATILE + (warp_n * 64) * ROWB + b_off;

#pragma unroll
        for (int kk = 0; kk < 4; kk++) {     // 4 x k16 per BK=64 chunk
            uint32_t a[2][4];
#pragma unroll
            for (int mi = 0; mi < 2; mi++)
                LDSM_X4(a[mi][0], a[mi][1], a[mi][2], a[mi][3],
                        sa + mi * 16 * ROWB + kk * 32);
            uint32_t b[4][4];
#pragma unroll
            for (int nt = 0; nt < 4; nt++)
                LDSM_X4(b[nt][0], b[nt][1], b[nt][2], b[nt][3],
                        sb + nt * 16 * ROWB + kk * 32);
#pragma unroll
            for (int mi = 0; mi < 2; mi++)
#pragma unroll
                for (int nt = 0; nt < 4; nt++) {
                    MMA_16816(cfr[mi][nt * 2 + 0],
                              a[mi][0], a[mi][1], a[mi][2], a[mi][3],
                              b[nt][0], b[nt][1]);
                    MMA_16816(cfr[mi][nt * 2 + 1],
                              a[mi][0], a[mi][1], a[mi][2], a[mi][3],
                              b[nt][2], b[nt][3]);
                }
        }

        CP_ASYNC_WAIT_ALL();
        __syncthreads();
    }

    // ---- epilogue: fragment -> gmem (float2 stores) ----
    const int rbase = row0 + warp_m * 32 + (lane >> 2);
    const int cbase = col0 + warp_n * 64 + (lane & 3) * 2;
#pragma unroll
    for (int mi = 0; mi < 2; mi++) {
#pragma unroll
        for (int ni = 0; ni < 8; ni++) {
            int r = rbase + mi * 16;
            int cc = cbase + ni * 8;
            if (r < M) {
                float2 o0 = make_float2(cfr[mi][ni][0] * outScale, cfr[mi][ni][1] * outScale);
                *(float2*)&C[(size_t)r * FEAT + cc] = o0;
            }
            if (r + 8 < M) {
                float2 o1 = make_float2(cfr[mi][ni][2] * outScale, cfr[mi][ni][3] * outScale);
                *(float2*)&C[(size_t)(r + 8) * FEAT + cc] = o1;
            }
        }
    }
}

// ---------------- edge pass 1: logits + segment max ----------------
__global__ void edge_attn_kernel(const float* __restrict__ q,
                                 const float* __restrict__ k,
                                 const float* __restrict__ bias,
                                 const int* __restrict__ src,
                                 const int* __restrict__ dst,
                                 float* __restrict__ attn,
                                 float* __restrict__ m, int E) {
    int e = (int)((blockIdx.x * (size_t)blockDim.x + threadIdx.x) >> 5);
    int lane = threadIdx.x & 31;
    if (e >= E) return;
    int sn = src[e], dn = dst[e];
    const float* kp = k + (size_t)sn * FEAT;
    const float* qp = q + (size_t)dn * FEAT;

    float sum[HEADS];
#pragma unroll
    for (int h = 0; h < HEADS; h++)
        sum[h] = kp[h * HEAD_DIM + lane] * qp[h * HEAD_DIM + lane];
#pragma unroll
    for (int h = 0; h < HEADS; h++) {
#pragma unroll
        for (int off = 16; off > 0; off >>= 1)
            sum[h] += __shfl_xor_sync(0xffffffffu, sum[h], off);
    }
    if (lane < HEADS) {
        float a = sum[lane] + bias[(size_t)e * HEADS + lane];
        attn[(size_t)e * HEADS + lane] = a;
        atomicMaxFloat(&m[dn * HEADS + lane], a);
    }
}

// ---------------- edge pass 2: exp, segment sum, scatter-add a*v[src] ----------------
__global__ void edge_accum_kernel(const float* __restrict__ v,
                                  const float* __restrict__ attn,
                                  const float* __restrict__ m,
                                  float* __restrict__ s_sum,
                                  float* __restrict__ acc,
                                  const int* __restrict__ src,
                                  const int* __restrict__ dst, int E) {
    int e = (int)((blockIdx.x * (size_t)blockDim.x + threadIdx.x) >> 5);
    int lane = threadIdx.x & 31;
    if (e >= E) return;
    int sn = src[e], dn = dst[e];

    float a = 0.0f;
    if (lane < HEADS) {
        a = expf(attn[(size_t)e * HEADS + lane] - m[dn * HEADS + lane]);
        atomicAdd(&s_sum[dn * HEADS + lane], a);
    }
    const float* vp = v + (size_t)sn * FEAT;
    float* ap = acc + (size_t)dn * FEAT;
#pragma unroll
    for (int h = 0; h < HEADS; h++) {
        float ah = __shfl_sync(0xffffffffu, a, h);
        atomicAdd(&ap[h * HEAD_DIM + lane], ah * vp[h * HEAD_DIM + lane]);
    }
}

// ---------------- launch ----------------
extern "C" void kernel_launch(void* const* d_in, const int* in_sizes, int n_in,
                              void* d_out, int out_size) {
    const float* nfeat = (const float*)d_in[0];
    const float* attn_bias = (const float*)d_in[1];
    const float* Wq = (const float*)d_in[2];
    const float* Wk = (const float*)d_in[3];
    const float* Wv = (const float*)d_in[4];
    const float* Wo = (const float*)d_in[5];
    const int* src = (const int*)d_in[6];
    const int* dst = (const int*)d_in[7];
    float* out = (float*)d_out;

    int N = in_sizes[0] / FEAT;
    int E = in_sizes[6];

    float *q, *k, *v, *acc, *attn, *m, *s;
    __nv_bfloat16 *a2, *acc2, *w2;
    cudaGetSymbolAddress((void**)&q, g_q);
    cudaGetSymbolAddress((void**)&k, g_k);
    cudaGetSymbolAddress((void**)&v, g_v);
    cudaGetSymbolAddress((void**)&acc, g_acc);
    cudaGetSymbolAddress((void**)&attn, g_attn);
    cudaGetSymbolAddress((void**)&m, g_m);
    cudaGetSymbolAddress((void**)&s, g_s);
    cudaGetSymbolAddress((void**)&a2, g_a2);
    cudaGetSymbolAddress((void**)&acc2, g_acc2);
    cudaGetSymbolAddress((void**)&w2, g_w2);

    cudaFuncSetAttribute(gemm_mma_kernel, cudaFuncAttributeMaxDynamicSharedMemorySize, GSMEM_BYTES);

    // init m/s/acc
    init_kernel<<<4096, 256>>>(m, s, acc, N * HEADS, N * FEAT);

    // conversions: nodes + 4 weight matrices
    int cblocks = (N * 64 + 255) / 256;
    conv_split_kernel<<<cblocks, 256>>>(nfeat, a2, nullptr, N);
    int wblocks = (256 * 768 + 255) / 256;
    conv_w_kernel<<<wblocks, 256>>>(Wq, w2 + 0 * (size_t)256 * 768);
    conv_w_kernel<<<wblocks, 256>>>(Wk, w2 + 1 * (size_t)256 * 768);
    conv_w_kernel<<<wblocks, 256>>>(Wv, w2 + 2 * (size_t)256 * 768);
    conv_w_kernel<<<wblocks, 256>>>(Wo, w2 + 3 * (size_t)256 * 768);

    // tensor-core projections
    dim3 ggrid(2, (N + 127) / 128);
    const float invScaling = 5.656854249492381f;  // sqrt(HEAD_DIM): reference DIVIDES q by scaling
    gemm_mma_kernel<<<ggrid, 256, GSMEM_BYTES>>>(a2, w2 + 0 * (size_t)256 * 768, q, N, invScaling);
    gemm_mma_kernel<<<ggrid, 256, GSMEM_BYTES>>>(a2, w2 + 1 * (size_t)256 * 768, k, N, 1.0f);
    gemm_mma_kernel<<<ggrid, 256, GSMEM_BYTES>>>(a2, w2 + 2 * (size_t)256 * 768, v, N, 1.0f);

    // edge passes (1 warp / edge)
    int eblocks = (E * 32 + 255) / 256;
    edge_attn_kernel<<<eblocks, 256>>>(q, k, attn_bias, src, dst, attn, m, E);
    edge_accum_kernel<<<eblocks, 256>>>(v, attn, m, s, acc, src, dst, E);

    // normalize acc by s during conversion, then final projection
    conv_split_kernel<<<cblocks, 256>>>(acc, acc2, s, N);
    gemm_mma_kernel<<<ggrid, 256, GSMEM_BYTES>>>(acc2, w2 + 3 * (size_t)256 * 768, out, N, 1.0f);
}

// round 5
// speedup vs baseline: 2.8992x; 1.1703x over previous
#include <cuda_runtime.h>
#include <cuda_bf16.h>
#include <math.h>
#include <stdint.h>

#define N_NODES 100000
#define FEAT    256
#define HEADS   8
#define HEAD_DIM 32
#define E_EDGES 800000
#define SMAX    56

// ---------------- scratch (no cudaMalloc allowed) ----------------
__device__ float g_q[(size_t)N_NODES * FEAT];
__device__ float g_k[(size_t)N_NODES * FEAT];
__device__ float g_v[(size_t)N_NODES * FEAT];
// bf16 hi/lo split inputs: [row][0..255]=hi, [row][256..511]=lo
__device__ __nv_bfloat16 g_a2[(size_t)N_NODES * 512];
__device__ __nv_bfloat16 g_acc2[(size_t)N_NODES * 512];
// W' = [Whi | Wlo | Whi], [256 rows][768 cols] bf16, per weight matrix
__device__ __nv_bfloat16 g_w2[4][(size_t)256 * 768];
// edge sort
__device__ int g_cnt[N_NODES];
__device__ int g_incl[N_NODES];
__device__ int g_off[N_NODES + 1];
__device__ int g_cur[N_NODES];
__device__ int g_eid[E_EDGES];
__device__ int g_bsum[128];

// ================= PTX helpers (all non-'a' baseline features) =================
__device__ __forceinline__ uint32_t smem_to_u32(const void* p) {
    uint32_t a;
    asm("{ .reg .u64 t; cvta.to.shared.u64 t, %1; cvt.u32.u64 %0, t; }" : "=r"(a) : "l"(p));
    return a;
}

#define LDSM_X4(r0, r1, r2, r3, addr) \
    asm volatile("ldmatrix.sync.aligned.m8n8.x4.shared.b16 {%0,%1,%2,%3}, [%4];" \
        : "=r"(r0), "=r"(r1), "=r"(r2), "=r"(r3) : "r"(addr))

#define MMA_16816(c, a0, a1, a2, a3, b0, b1) \
    asm volatile("mma.sync.aligned.m16n8k16.row.col.f32.bf16.bf16.f32 " \
        "{%0,%1,%2,%3}, {%4,%5,%6,%7}, {%8,%9}, {%0,%1,%2,%3};" \
        : "+f"((c)[0]), "+f"((c)[1]), "+f"((c)[2]), "+f"((c)[3]) \
        : "r"(a0), "r"(a1), "r"(a2), "r"(a3), "r"(b0), "r"(b1))

__device__ __forceinline__ void cp_async16(uint32_t dst, const void* src, uint32_t src_size) {
    asm volatile("cp.async.cg.shared.global [%0], [%1], 16, %2;"
        :: "r"(dst), "l"(src), "r"(src_size) : "memory");
}
#define CP_ASYNC_COMMIT() asm volatile("cp.async.commit_group;" ::: "memory")
#define CP_ASYNC_WAIT_ALL() asm volatile("cp.async.wait_group 0;" ::: "memory")

// ---------------- fp32 -> bf16 hi/lo split (nodes) ----------------
__global__ void conv_split_kernel(const float* __restrict__ X,
                                  __nv_bfloat16* __restrict__ Y,
                                  int rows) {
    int i = blockIdx.x * blockDim.x + threadIdx.x;   // one per float4: rows*64
    int tot = rows * 64;
    if (i >= tot) return;
    int row = i >> 6, qq = i & 63;
    float4 x = ((const float4*)X)[i];
    __nv_bfloat16 h0 = __float2bfloat16(x.x), h1 = __float2bfloat16(x.y);
    __nv_bfloat16 h2 = __float2bfloat16(x.z), h3 = __float2bfloat16(x.w);
    __nv_bfloat16 l0 = __float2bfloat16(x.x - __bfloat162float(h0));
    __nv_bfloat16 l1 = __float2bfloat16(x.y - __bfloat162float(h1));
    __nv_bfloat16 l2 = __float2bfloat16(x.z - __bfloat162float(h2));
    __nv_bfloat16 l3 = __float2bfloat16(x.w - __bfloat162float(h3));
    uint32_t hA = ((uint32_t)__bfloat16_as_ushort(h1) << 16) | __bfloat16_as_ushort(h0);
    uint32_t hB = ((uint32_t)__bfloat16_as_ushort(h3) << 16) | __bfloat16_as_ushort(h2);
    uint32_t lA = ((uint32_t)__bfloat16_as_ushort(l1) << 16) | __bfloat16_as_ushort(l0);
    uint32_t lB = ((uint32_t)__bfloat16_as_ushort(l3) << 16) | __bfloat16_as_ushort(l2);
    size_t base = (size_t)row * 512 + qq * 4;
    *(uint2*)(Y + base)       = make_uint2(hA, hB);
    *(uint2*)(Y + base + 256) = make_uint2(lA, lB);
}

// ---------------- W -> W' = [Whi | Wlo | Whi], [256][768] bf16, 4 mats fused ----------------
__global__ void conv_w_kernel(const float* __restrict__ W0, const float* __restrict__ W1,
                              const float* __restrict__ W2p, const float* __restrict__ W3,
                              __nv_bfloat16* __restrict__ OUT) {
    int i = blockIdx.x * blockDim.x + threadIdx.x;   // 256*768 per matrix
    if (i >= 256 * 768) return;
    int which = blockIdx.y;
    const float* W = (which == 0) ? W0 : (which == 1) ? W1 : (which == 2) ? W2p : W3;
    int n = i / 768, kc = i % 768;
    int sk = (kc < 256) ? kc : ((kc < 512) ? kc - 256 : kc - 512);
    float w = W[n * 256 + sk];
    __nv_bfloat16 hi = __float2bfloat16(w);
    __nv_bfloat16 res;
    if (kc < 256 || kc >= 512) res = hi;
    else res = __float2bfloat16(w - __bfloat162float(hi));
    OUT[(size_t)which * 256 * 768 + (size_t)n * 768 + kc] = res;
}

// ---------------- HMMA GEMM: C[M,256] = A2split @ W2'^T * outScale ----------------
#define NCHUNK 12
#define ROWB   144
#define ATILE  (128 * ROWB)
#define STAGE  (2 * ATILE)
#define GSMEM_BYTES (2 * STAGE)

__global__ __launch_bounds__(256, 2) void gemm_mma_kernel(
        const __nv_bfloat16* __restrict__ A2,
        const __nv_bfloat16* __restrict__ W2,
        float* __restrict__ C,
        int M, float outScale) {
    extern __shared__ __align__(16) char smem[];
    const uint32_t sbase = smem_to_u32(smem);

    const int tid = threadIdx.x;
    const int lane = tid & 31;
    const int wid = tid >> 5;
    const int warp_m = wid & 3;
    const int warp_n = wid >> 2;
    const int row0 = blockIdx.y * 128;
    const int col0 = blockIdx.x * 128;

    const int lq = tid & 7;
    const int lr0 = tid >> 3;

    const uint32_t a_off = (uint32_t)((lane & 15) * ROWB + ((lane & 16) ? 16 : 0));
    const uint32_t b_off = (uint32_t)(((lane & 7) + ((lane & 16) ? 8 : 0)) * ROWB +
                                      ((lane & 8) ? 16 : 0));

    float cfr[2][8][4];
#pragma unroll
    for (int mi = 0; mi < 2; mi++)
#pragma unroll
        for (int ni = 0; ni < 8; ni++)
#pragma unroll
            for (int j = 0; j < 4; j++) cfr[mi][ni][j] = 0.0f;

    auto issue_loads = [&](int c, int stage_idx) {
        const int srcoff = ((c < 8) ? 0 : 256) + (c & 3) * 64;
        const uint32_t sa = sbase + stage_idx * STAGE;
        const uint32_t sb = sa + ATILE;
#pragma unroll
        for (int it = 0; it < 4; it++) {
            int r = lr0 + it * 32;
            int gr = row0 + r;
            uint32_t ok = (gr < M) ? 16u : 0u;
            int grc = (gr < M) ? gr : 0;
            cp_async16(sa + r * ROWB + lq * 16,
                       A2 + (size_t)grc * 512 + srcoff + lq * 8, ok);
            cp_async16(sb + r * ROWB + lq * 16,
                       W2 + (size_t)(col0 + r) * 768 + c * 64 + lq * 8, 16u);
        }
        CP_ASYNC_COMMIT();
    };

    issue_loads(0, 0);
    CP_ASYNC_WAIT_ALL();
    __syncthreads();

    for (int c = 0; c < NCHUNK; c++) {
        if (c + 1 < NCHUNK) issue_loads(c + 1, (c + 1) & 1);

        const uint32_t sa = sbase + (c & 1) * STAGE + (warp_m * 32) * ROWB + a_off;
        const uint32_t sb = sbase + (c & 1) * STAGE + ATILE + (warp_n * 64) * ROWB + b_off;

#pragma unroll
        for (int kk = 0; kk < 4; kk++) {
            uint32_t a[2][4];
#pragma unroll
            for (int mi = 0; mi < 2; mi++)
                LDSM_X4(a[mi][0], a[mi][1], a[mi][2], a[mi][3],
                        sa + mi * 16 * ROWB + kk * 32);
            uint32_t b[4][4];
#pragma unroll
            for (int nt = 0; nt < 4; nt++)
                LDSM_X4(b[nt][0], b[nt][1], b[nt][2], b[nt][3],
                        sb + nt * 16 * ROWB + kk * 32);
#pragma unroll
            for (int mi = 0; mi < 2; mi++)
#pragma unroll
                for (int nt = 0; nt < 4; nt++) {
                    MMA_16816(cfr[mi][nt * 2 + 0],
                              a[mi][0], a[mi][1], a[mi][2], a[mi][3],
                              b[nt][0], b[nt][1]);
                    MMA_16816(cfr[mi][nt * 2 + 1],
                              a[mi][0], a[mi][1], a[mi][2], a[mi][3],
                              b[nt][2], b[nt][3]);
                }
        }

        CP_ASYNC_WAIT_ALL();
        __syncthreads();
    }

    const int rbase = row0 + warp_m * 32 + (lane >> 2);
    const int cbase = col0 + warp_n * 64 + (lane & 3) * 2;
#pragma unroll
    for (int mi = 0; mi < 2; mi++) {
#pragma unroll
        for (int ni = 0; ni < 8; ni++) {
            int r = rbase + mi * 16;
            int cc = cbase + ni * 8;
            if (r < M) {
                float2 o0 = make_float2(cfr[mi][ni][0] * outScale, cfr[mi][ni][1] * outScale);
                *(float2*)&C[(size_t)r * FEAT + cc] = o0;
            }
            if (r + 8 < M) {
                float2 o1 = make_float2(cfr[mi][ni][2] * outScale, cfr[mi][ni][3] * outScale);
                *(float2*)&C[(size_t)(r + 8) * FEAT + cc] = o1;
            }
        }
    }
}

// ================= edge sort: counting sort by dst =================
__global__ void zero_cnt_kernel(int* cnt, int n) {
    int i = blockIdx.x * blockDim.x + threadIdx.x;
    if (i < n) cnt[i] = 0;
}
__global__ void hist_kernel(const int* __restrict__ dst, int* cnt, int E) {
    int e = blockIdx.x * blockDim.x + threadIdx.x;
    if (e < E) atomicAdd(&cnt[dst[e]], 1);
}
// inclusive scan of cnt per 1024-block, block totals to bsum
__global__ void scan1_kernel(const int* __restrict__ cnt, int* incl, int* bsum, int n) {
    __shared__ int sm[1024];
    int i = blockIdx.x * 1024 + threadIdx.x;
    int val = (i < n) ? cnt[i] : 0;
    sm[threadIdx.x] = val;
    __syncthreads();
#pragma unroll
    for (int off = 1; off < 1024; off <<= 1) {
        int t = (threadIdx.x >= off) ? sm[threadIdx.x - off] : 0;
        __syncthreads();
        sm[threadIdx.x] += t;
        __syncthreads();
    }
    if (i < n) incl[i] = sm[threadIdx.x];
    if (threadIdx.x == 1023) bsum[blockIdx.x] = sm[1023];
}
// exclusive scan of block sums (<=128 blocks), in place
__global__ void scan2_kernel(int* bsum, int nb) {
    __shared__ int sm[128];
    int t = threadIdx.x;
    int v = (t < nb) ? bsum[t] : 0;
    sm[t] = v;
    __syncthreads();
#pragma unroll
    for (int off = 1; off < 128; off <<= 1) {
        int u = (t >= off) ? sm[t - off] : 0;
        __syncthreads();
        sm[t] += u;
        __syncthreads();
    }
    if (t < nb) bsum[t] = sm[t] - v;   // exclusive
}
// finalize offsets and cursors
__global__ void scan3_kernel(const int* __restrict__ incl, const int* __restrict__ bsum,
                             const int* __restrict__ cnt, int* off, int* cur, int n) {
    int i = blockIdx.x * blockDim.x + threadIdx.x;
    if (i == 0) off[0] = 0;
    if (i < n) {
        int o = incl[i] + bsum[i >> 10];
        off[i + 1] = o;
        cur[i] = o - cnt[i];
    }
}
__global__ void scatter_kernel(const int* __restrict__ dst, int* cur, int* eid, int E) {
    int e = blockIdx.x * blockDim.x + threadIdx.x;
    if (e < E) {
        int pos = atomicAdd(&cur[dst[e]], 1);
        eid[pos] = e;
    }
}

// ================= fused edge kernel: warp per dst =================
// logits -> segment max -> exp/sum -> normalized a.v accumulate -> bf16 split store
__global__ __launch_bounds__(256) void edge_fused_kernel(
        const float* __restrict__ q,
        const float* __restrict__ k,
        const float* __restrict__ v,
        const float* __restrict__ bias,
        const int* __restrict__ src,
        const int* __restrict__ off,
        const int* __restrict__ eid,
        __nv_bfloat16* __restrict__ acc2,
        int N) {
    __shared__ float slog[8][SMAX * 8];
    int gw = (int)((blockIdx.x * (size_t)blockDim.x + threadIdx.x) >> 5);
    int lane = threadIdx.x & 31;
    int wib = threadIdx.x >> 5;
    if (gw >= N) return;
    const int d = gw;
    const int beg = off[d], end = off[d + 1];
    const int deg = end - beg;
    const int h = lane >> 2;                  // head 0..7 (4 lanes per head)

    // q row: lane holds cols lane*8 .. lane*8+7 (head h, dims (lane&3)*8..+8)
    const float4* qp = (const float4*)(q + (size_t)d * FEAT);
    float4 q0, q1;
    float mh = -INFINITY;
    const bool fits = (deg <= SMAX);

    if (deg > 0) {
        q0 = qp[lane * 2];
        q1 = qp[lane * 2 + 1];
        // ---- pass 1: logits + max ----
        for (int i = 0; i < deg; i++) {
            int e = eid[beg + i];
            int sn = src[e];
            const float4* kp = (const float4*)(k + (size_t)sn * FEAT);
            float4 k0 = kp[lane * 2], k1 = kp[lane * 2 + 1];
            float ds = q0.x * k0.x + q0.y * k0.y + q0.z * k0.z + q0.w * k0.w
                     + q1.x * k1.x + q1.y * k1.y + q1.z * k1.z + q1.w * k1.w;
            ds += __shfl_xor_sync(0xffffffffu, ds, 1);
            ds += __shfl_xor_sync(0xffffffffu, ds, 2);
            float l = ds + __ldg(&bias[(size_t)e * HEADS + h]);
            mh = fmaxf(mh, l);
            if (fits && (lane & 3) == 0) slog[wib][i * 8 + h] = l;
        }
    }

    // ---- pass 2: exp, sum, weighted v accumulate ----
    float acc[8] = {0, 0, 0, 0, 0, 0, 0, 0};
    float ssum = 0.0f;
    for (int i = 0; i < deg; i++) {
        int e = eid[beg + i];
        int sn = src[e];
        float l;
        if (fits) {
            l = slog[wib][i * 8 + h];
        } else {
            const float4* kp = (const float4*)(k + (size_t)sn * FEAT);
            float4 k0 = kp[lane * 2], k1 = kp[lane * 2 + 1];
            float ds = q0.x * k0.x + q0.y * k0.y + q0.z * k0.z + q0.w * k0.w
                     + q1.x * k1.x + q1.y * k1.y + q1.z * k1.z + q1.w * k1.w;
            ds += __shfl_xor_sync(0xffffffffu, ds, 1);
            ds += __shfl_xor_sync(0xffffffffu, ds, 2);
            l = ds + __ldg(&bias[(size_t)e * HEADS + h]);
        }
        float a = __expf(l - mh);
        ssum += a;
        const float4* vp = (const float4*)(v + (size_t)sn * FEAT);
        float4 v0 = vp[lane * 2], v1 = vp[lane * 2 + 1];
        acc[0] = fmaf(a, v0.x, acc[0]);
        acc[1] = fmaf(a, v0.y, acc[1]);
        acc[2] = fmaf(a, v0.z, acc[2]);
        acc[3] = fmaf(a, v0.w, acc[3]);
        acc[4] = fmaf(a, v1.x, acc[4]);
        acc[5] = fmaf(a, v1.y, acc[5]);
        acc[6] = fmaf(a, v1.z, acc[6]);
        acc[7] = fmaf(a, v1.w, acc[7]);
    }

    float r = (deg > 0) ? (1.0f / ssum) : 0.0f;

    // ---- normalized bf16 hi/lo split store ----
    float o[8];
#pragma unroll
    for (int j = 0; j < 8; j++) o[j] = acc[j] * r;
    __nv_bfloat16 hi[8], lo[8];
#pragma unroll
    for (int j = 0; j < 8; j++) {
        hi[j] = __float2bfloat16(o[j]);
        lo[j] = __float2bfloat16(o[j] - __bfloat162float(hi[j]));
    }
    uint4 hv, lv;
    hv.x = ((uint32_t)__bfloat16_as_ushort(hi[1]) << 16) | __bfloat16_as_ushort(hi[0]);
    hv.y = ((uint32_t)__bfloat16_as_ushort(hi[3]) << 16) | __bfloat16_as_ushort(hi[2]);
    hv.z = ((uint32_t)__bfloat16_as_ushort(hi[5]) << 16) | __bfloat16_as_ushort(hi[4]);
    hv.w = ((uint32_t)__bfloat16_as_ushort(hi[7]) << 16) | __bfloat16_as_ushort(hi[6]);
    lv.x = ((uint32_t)__bfloat16_as_ushort(lo[1]) << 16) | __bfloat16_as_ushort(lo[0]);
    lv.y = ((uint32_t)__bfloat16_as_ushort(lo[3]) << 16) | __bfloat16_as_ushort(lo[2]);
    lv.z = ((uint32_t)__bfloat16_as_ushort(lo[5]) << 16) | __bfloat16_as_ushort(lo[4]);
    lv.w = ((uint32_t)__bfloat16_as_ushort(lo[7]) << 16) | __bfloat16_as_ushort(lo[6]);
    *(uint4*)(acc2 + (size_t)d * 512 + lane * 8)       = hv;
    *(uint4*)(acc2 + (size_t)d * 512 + 256 + lane * 8) = lv;
}

// ---------------- launch ----------------
extern "C" void kernel_launch(void* const* d_in, const int* in_sizes, int n_in,
                              void* d_out, int out_size) {
    const float* nfeat = (const float*)d_in[0];
    const float* attn_bias = (const float*)d_in[1];
    const float* Wq = (const float*)d_in[2];
    const float* Wk = (const float*)d_in[3];
    const float* Wv = (const float*)d_in[4];
    const float* Wo = (const float*)d_in[5];
    const int* src = (const int*)d_in[6];
    const int* dst = (const int*)d_in[7];
    float* out = (float*)d_out;

    int N = in_sizes[0] / FEAT;
    int E = in_sizes[6];

    float *q, *k, *v;
    __nv_bfloat16 *a2, *acc2, *w2;
    int *cnt, *incl, *off, *cur, *eid, *bsum;
    cudaGetSymbolAddress((void**)&q, g_q);
    cudaGetSymbolAddress((void**)&k, g_k);
    cudaGetSymbolAddress((void**)&v, g_v);
    cudaGetSymbolAddress((void**)&a2, g_a2);
    cudaGetSymbolAddress((void**)&acc2, g_acc2);
    cudaGetSymbolAddress((void**)&w2, g_w2);
    cudaGetSymbolAddress((void**)&cnt, g_cnt);
    cudaGetSymbolAddress((void**)&incl, g_incl);
    cudaGetSymbolAddress((void**)&off, g_off);
    cudaGetSymbolAddress((void**)&cur, g_cur);
    cudaGetSymbolAddress((void**)&eid, g_eid);
    cudaGetSymbolAddress((void**)&bsum, g_bsum);

    cudaFuncSetAttribute(gemm_mma_kernel, cudaFuncAttributeMaxDynamicSharedMemorySize, GSMEM_BYTES);

    // ---- edge counting sort by dst ----
    int nb1024 = (N + 1023) / 1024;
    zero_cnt_kernel<<<(N + 255) / 256, 256>>>(cnt, N);
    hist_kernel<<<(E + 255) / 256, 256>>>(dst, cnt, E);
    scan1_kernel<<<nb1024, 1024>>>(cnt, incl, bsum, N);
    scan2_kernel<<<1, 128>>>(bsum, nb1024);
    scan3_kernel<<<(N + 255) / 256, 256>>>(incl, bsum, cnt, off, cur, N);
    scatter_kernel<<<(E + 255) / 256, 256>>>(dst, cur, eid, E);

    // ---- conversions ----
    int cblocks = (N * 64 + 255) / 256;
    conv_split_kernel<<<cblocks, 256>>>(nfeat, a2, N);
    dim3 wgrid((256 * 768 + 255) / 256, 4);
    conv_w_kernel<<<wgrid, 256>>>(Wq, Wk, Wv, Wo, w2);

    // ---- tensor-core projections ----
    dim3 ggrid(2, (N + 127) / 128);
    const float invScaling = 5.656854249492381f;  // sqrt(HEAD_DIM): reference DIVIDES q by scaling
    gemm_mma_kernel<<<ggrid, 256, GSMEM_BYTES>>>(a2, w2 + 0 * (size_t)256 * 768, q, N, invScaling);
    gemm_mma_kernel<<<ggrid, 256, GSMEM_BYTES>>>(a2, w2 + 1 * (size_t)256 * 768, k, N, 1.0f);
    gemm_mma_kernel<<<ggrid, 256, GSMEM_BYTES>>>(a2, w2 + 2 * (size_t)256 * 768, v, N, 1.0f);

    // ---- fused edge softmax + aggregate (no atomics), writes bf16 split acc2 ----
    int fblocks = (N + 7) / 8;   // 8 warps per block, warp per dst
    edge_fused_kernel<<<fblocks, 256>>>(q, k, v, attn_bias, src, off, eid, acc2, N);

    // ---- final projection ----
    gemm_mma_kernel<<<ggrid, 256, GSMEM_BYTES>>>(acc2, w2 + 3 * (size_t)256 * 768, out, N, 1.0f);
}

// round 6
// speedup vs baseline: 3.0646x; 1.0570x over previous
#include <cuda_runtime.h>
#include <cuda_bf16.h>
#include <math.h>
#include <stdint.h>

#define N_NODES 100000
#define FEAT    256
#define HEADS   8
#define HEAD_DIM 32
#define E_EDGES 800000
#define SMAX    56

// ---------------- scratch (no cudaMalloc allowed) ----------------
__device__ float g_q[(size_t)N_NODES * FEAT];
__device__ float g_k[(size_t)N_NODES * FEAT];
__device__ float g_v[(size_t)N_NODES * FEAT];
__device__ __nv_bfloat16 g_a2[(size_t)N_NODES * 512];
__device__ __nv_bfloat16 g_acc2[(size_t)N_NODES * 512];
__device__ __nv_bfloat16 g_w2[4][(size_t)256 * 768];
// edge sort
__device__ int g_cnt[N_NODES];
__device__ int g_incl[N_NODES];
__device__ int g_off[N_NODES + 1];
__device__ int g_cur[N_NODES];
__device__ int g_eid[E_EDGES];
__device__ int g_bsum[128];

// ================= PTX helpers =================
__device__ __forceinline__ uint32_t smem_to_u32(const void* p) {
    uint32_t a;
    asm("{ .reg .u64 t; cvta.to.shared.u64 t, %1; cvt.u32.u64 %0, t; }" : "=r"(a) : "l"(p));
    return a;
}

#define LDSM_X4(r0, r1, r2, r3, addr) \
    asm volatile("ldmatrix.sync.aligned.m8n8.x4.shared.b16 {%0,%1,%2,%3}, [%4];" \
        : "=r"(r0), "=r"(r1), "=r"(r2), "=r"(r3) : "r"(addr))

#define MMA_16816(c, a0, a1, a2, a3, b0, b1) \
    asm volatile("mma.sync.aligned.m16n8k16.row.col.f32.bf16.bf16.f32 " \
        "{%0,%1,%2,%3}, {%4,%5,%6,%7}, {%8,%9}, {%0,%1,%2,%3};" \
        : "+f"((c)[0]), "+f"((c)[1]), "+f"((c)[2]), "+f"((c)[3]) \
        : "r"(a0), "r"(a1), "r"(a2), "r"(a3), "r"(b0), "r"(b1))

__device__ __forceinline__ void cp_async16(uint32_t dst, const void* src, uint32_t src_size) {
    asm volatile("cp.async.cg.shared.global [%0], [%1], 16, %2;"
        :: "r"(dst), "l"(src), "r"(src_size) : "memory");
}
#define CP_ASYNC_COMMIT() asm volatile("cp.async.commit_group;" ::: "memory")
#define CP_ASYNC_WAIT_ALL() asm volatile("cp.async.wait_group 0;" ::: "memory")

// ---------------- fp32 -> bf16 hi/lo split (nodes) ----------------
__global__ void conv_split_kernel(const float* __restrict__ X,
                                  __nv_bfloat16* __restrict__ Y,
                                  int rows) {
    int i = blockIdx.x * blockDim.x + threadIdx.x;
    int tot = rows * 64;
    if (i >= tot) return;
    int row = i >> 6, qq = i & 63;
    float4 x = ((const float4*)X)[i];
    __nv_bfloat16 h0 = __float2bfloat16(x.x), h1 = __float2bfloat16(x.y);
    __nv_bfloat16 h2 = __float2bfloat16(x.z), h3 = __float2bfloat16(x.w);
    __nv_bfloat16 l0 = __float2bfloat16(x.x - __bfloat162float(h0));
    __nv_bfloat16 l1 = __float2bfloat16(x.y - __bfloat162float(h1));
    __nv_bfloat16 l2 = __float2bfloat16(x.z - __bfloat162float(h2));
    __nv_bfloat16 l3 = __float2bfloat16(x.w - __bfloat162float(h3));
    uint32_t hA = ((uint32_t)__bfloat16_as_ushort(h1) << 16) | __bfloat16_as_ushort(h0);
    uint32_t hB = ((uint32_t)__bfloat16_as_ushort(h3) << 16) | __bfloat16_as_ushort(h2);
    uint32_t lA = ((uint32_t)__bfloat16_as_ushort(l1) << 16) | __bfloat16_as_ushort(l0);
    uint32_t lB = ((uint32_t)__bfloat16_as_ushort(l3) << 16) | __bfloat16_as_ushort(l2);
    size_t base = (size_t)row * 512 + qq * 4;
    *(uint2*)(Y + base)       = make_uint2(hA, hB);
    *(uint2*)(Y + base + 256) = make_uint2(lA, lB);
}

// ---------------- W -> W' = [Whi | Wlo | Whi], 4 mats fused ----------------
__global__ void conv_w_kernel(const float* __restrict__ W0, const float* __restrict__ W1,
                              const float* __restrict__ W2p, const float* __restrict__ W3,
                              __nv_bfloat16* __restrict__ OUT) {
    int i = blockIdx.x * blockDim.x + threadIdx.x;
    if (i >= 256 * 768) return;
    int which = blockIdx.y;
    const float* W = (which == 0) ? W0 : (which == 1) ? W1 : (which == 2) ? W2p : W3;
    int n = i / 768, kc = i % 768;
    int sk = (kc < 256) ? kc : ((kc < 512) ? kc - 256 : kc - 512);
    float w = W[n * 256 + sk];
    __nv_bfloat16 hi = __float2bfloat16(w);
    __nv_bfloat16 res;
    if (kc < 256 || kc >= 512) res = hi;
    else res = __float2bfloat16(w - __bfloat162float(hi));
    OUT[(size_t)which * 256 * 768 + (size_t)n * 768 + kc] = res;
}

// ---------------- HMMA GEMM: C[M,256] = A2split @ W2'^T * outScale ----------------
#define NCHUNK 12
#define ROWB   144
#define ATILE  (128 * ROWB)
#define STAGE  (2 * ATILE)
#define GSMEM_BYTES (2 * STAGE)

__global__ __launch_bounds__(256, 2) void gemm_mma_kernel(
        const __nv_bfloat16* __restrict__ A2,
        const __nv_bfloat16* __restrict__ W2,
        float* __restrict__ C,
        int M, float outScale) {
    extern __shared__ __align__(16) char smem[];
    const uint32_t sbase = smem_to_u32(smem);

    const int tid = threadIdx.x;
    const int lane = tid & 31;
    const int wid = tid >> 5;
    const int warp_m = wid & 3;
    const int warp_n = wid >> 2;
    const int row0 = blockIdx.y * 128;
    const int col0 = blockIdx.x * 128;

    const int lq = tid & 7;
    const int lr0 = tid >> 3;

    const uint32_t a_off = (uint32_t)((lane & 15) * ROWB + ((lane & 16) ? 16 : 0));
    const uint32_t b_off = (uint32_t)(((lane & 7) + ((lane & 16) ? 8 : 0)) * ROWB +
                                      ((lane & 8) ? 16 : 0));

    float cfr[2][8][4];
#pragma unroll
    for (int mi = 0; mi < 2; mi++)
#pragma unroll
        for (int ni = 0; ni < 8; ni++)
#pragma unroll
            for (int j = 0; j < 4; j++) cfr[mi][ni][j] = 0.0f;

    auto issue_loads = [&](int c, int stage_idx) {
        const int srcoff = ((c < 8) ? 0 : 256) + (c & 3) * 64;
        const uint32_t sa = sbase + stage_idx * STAGE;
        const uint32_t sb = sa + ATILE;
#pragma unroll
        for (int it = 0; it < 4; it++) {
            int r = lr0 + it * 32;
            int gr = row0 + r;
            uint32_t ok = (gr < M) ? 16u : 0u;
            int grc = (gr < M) ? gr : 0;
            cp_async16(sa + r * ROWB + lq * 16,
                       A2 + (size_t)grc * 512 + srcoff + lq * 8, ok);
            cp_async16(sb + r * ROWB + lq * 16,
                       W2 + (size_t)(col0 + r) * 768 + c * 64 + lq * 8, 16u);
        }
        CP_ASYNC_COMMIT();
    };

    issue_loads(0, 0);
    CP_ASYNC_WAIT_ALL();
    __syncthreads();

    for (int c = 0; c < NCHUNK; c++) {
        if (c + 1 < NCHUNK) issue_loads(c + 1, (c + 1) & 1);

        const uint32_t sa = sbase + (c & 1) * STAGE + (warp_m * 32) * ROWB + a_off;
        const uint32_t sb = sbase + (c & 1) * STAGE + ATILE + (warp_n * 64) * ROWB + b_off;

#pragma unroll
        for (int kk = 0; kk < 4; kk++) {
            uint32_t a[2][4];
#pragma unroll
            for (int mi = 0; mi < 2; mi++)
                LDSM_X4(a[mi][0], a[mi][1], a[mi][2], a[mi][3],
                        sa + mi * 16 * ROWB + kk * 32);
            uint32_t b[4][4];
#pragma unroll
            for (int nt = 0; nt < 4; nt++)
                LDSM_X4(b[nt][0], b[nt][1], b[nt][2], b[nt][3],
                        sb + nt * 16 * ROWB + kk * 32);
#pragma unroll
            for (int mi = 0; mi < 2; mi++)
#pragma unroll
                for (int nt = 0; nt < 4; nt++) {
                    MMA_16816(cfr[mi][nt * 2 + 0],
                              a[mi][0], a[mi][1], a[mi][2], a[mi][3],
                              b[nt][0], b[nt][1]);
                    MMA_16816(cfr[mi][nt * 2 + 1],
                              a[mi][0], a[mi][1], a[mi][2], a[mi][3],
                              b[nt][2], b[nt][3]);
                }
        }

        CP_ASYNC_WAIT_ALL();
        __syncthreads();
    }

    const int rbase = row0 + warp_m * 32 + (lane >> 2);
    const int cbase = col0 + warp_n * 64 + (lane & 3) * 2;
#pragma unroll
    for (int mi = 0; mi < 2; mi++) {
#pragma unroll
        for (int ni = 0; ni < 8; ni++) {
            int r = rbase + mi * 16;
            int cc = cbase + ni * 8;
            if (r < M) {
                float2 o0 = make_float2(cfr[mi][ni][0] * outScale, cfr[mi][ni][1] * outScale);
                *(float2*)&C[(size_t)r * FEAT + cc] = o0;
            }
            if (r + 8 < M) {
                float2 o1 = make_float2(cfr[mi][ni][2] * outScale, cfr[mi][ni][3] * outScale);
                *(float2*)&C[(size_t)(r + 8) * FEAT + cc] = o1;
            }
        }
    }
}

// ================= edge sort: counting sort by dst =================
__global__ void zero_cnt_kernel(int* cnt, int n) {
    int i = blockIdx.x * blockDim.x + threadIdx.x;
    if (i < n) cnt[i] = 0;
}
__global__ void hist_kernel(const int* __restrict__ dst, int* cnt, int E) {
    int e = blockIdx.x * blockDim.x + threadIdx.x;
    if (e < E) atomicAdd(&cnt[dst[e]], 1);
}
__global__ void scan1_kernel(const int* __restrict__ cnt, int* incl, int* bsum, int n) {
    __shared__ int sm[1024];
    int i = blockIdx.x * 1024 + threadIdx.x;
    int val = (i < n) ? cnt[i] : 0;
    sm[threadIdx.x] = val;
    __syncthreads();
#pragma unroll
    for (int off = 1; off < 1024; off <<= 1) {
        int t = (threadIdx.x >= off) ? sm[threadIdx.x - off] : 0;
        __syncthreads();
        sm[threadIdx.x] += t;
        __syncthreads();
    }
    if (i < n) incl[i] = sm[threadIdx.x];
    if (threadIdx.x == 1023) bsum[blockIdx.x] = sm[1023];
}
__global__ void scan2_kernel(int* bsum, int nb) {
    __shared__ int sm[128];
    int t = threadIdx.x;
    int v = (t < nb) ? bsum[t] : 0;
    sm[t] = v;
    __syncthreads();
#pragma unroll
    for (int off = 1; off < 128; off <<= 1) {
        int u = (t >= off) ? sm[t - off] : 0;
        __syncthreads();
        sm[t] += u;
        __syncthreads();
    }
    if (t < nb) bsum[t] = sm[t] - v;
}
__global__ void scan3_kernel(const int* __restrict__ incl, const int* __restrict__ bsum,
                             const int* __restrict__ cnt, int* off, int* cur, int n) {
    int i = blockIdx.x * blockDim.x + threadIdx.x;
    if (i == 0) off[0] = 0;
    if (i < n) {
        int o = incl[i] + bsum[i >> 10];
        off[i + 1] = o;
        cur[i] = o - cnt[i];
    }
}
__global__ void scatter_kernel(const int* __restrict__ dst, int* cur, int* eid, int E) {
    int e = blockIdx.x * blockDim.x + threadIdx.x;
    if (e < E) {
        int pos = atomicAdd(&cur[dst[e]], 1);
        eid[pos] = e;
    }
}

// ================= fused edge kernel: warp per dst =================
__global__ __launch_bounds__(256) void edge_fused_kernel(
        const float* __restrict__ q,
        const float* __restrict__ k,
        const float* __restrict__ v,
        const float* __restrict__ bias,
        const int* __restrict__ src,
        const int* __restrict__ off,
        const int* __restrict__ eid,
        __nv_bfloat16* __restrict__ acc2,
        int N) {
    __shared__ float slog[8][SMAX * 8];
    const unsigned FULL = 0xffffffffu;
    int gw = (int)((blockIdx.x * (size_t)blockDim.x + threadIdx.x) >> 5);
    int lane = threadIdx.x & 31;
    int wib = threadIdx.x >> 5;
    if (gw >= N) return;
    const int d = gw;
    const int beg = off[d], end = off[d + 1];
    const int deg = end - beg;
    const int h = lane >> 2;

    const float4* qp = (const float4*)(q + (size_t)d * FEAT);
    float4 q0, q1;
    float mh = -INFINITY;
    const bool fits = (deg <= SMAX);

    if (deg > 0) {
        q0 = qp[lane * 2];
        q1 = qp[lane * 2 + 1];
        // ---- pass 1: logits + max (staged eid/src, shfl broadcast) ----
        for (int base = 0; base < deg; base += 32) {
            int cnt = min(32, deg - base);
            int e_l = 0, s_l = 0;
            if (lane < cnt) {
                e_l = __ldg(&eid[beg + base + lane]);
                s_l = __ldg(&src[e_l]);
            }
            for (int i = 0; i < cnt; i++) {
                int e = __shfl_sync(FULL, e_l, i);
                int sn = __shfl_sync(FULL, s_l, i);
                const float4* kp = (const float4*)(k + (size_t)sn * FEAT);
                float4 k0 = kp[lane * 2], k1 = kp[lane * 2 + 1];
                float ds = q0.x * k0.x + q0.y * k0.y + q0.z * k0.z + q0.w * k0.w
                         + q1.x * k1.x + q1.y * k1.y + q1.z * k1.z + q1.w * k1.w;
                ds += __shfl_xor_sync(FULL, ds, 1);
                ds += __shfl_xor_sync(FULL, ds, 2);
                float l = ds + __ldg(&bias[(size_t)e * HEADS + h]);
                mh = fmaxf(mh, l);
                if (fits && (lane & 3) == 0) slog[wib][(base + i) * 8 + h] = l;
            }
        }
    }

    // ---- pass 2: exp, sum, weighted v accumulate ----
    float acc[8] = {0, 0, 0, 0, 0, 0, 0, 0};
    float ssum = 0.0f;
    for (int base = 0; base < deg; base += 32) {
        int cnt = min(32, deg - base);
        int e_l = 0, s_l = 0;
        if (lane < cnt) {
            e_l = __ldg(&eid[beg + base + lane]);
            s_l = __ldg(&src[e_l]);
        }
        for (int i = 0; i < cnt; i++) {
            int e = __shfl_sync(FULL, e_l, i);
            int sn = __shfl_sync(FULL, s_l, i);
            float l;
            if (fits) {
                l = slog[wib][(base + i) * 8 + h];
            } else {
                const float4* kp = (const float4*)(k + (size_t)sn * FEAT);
                float4 k0 = kp[lane * 2], k1 = kp[lane * 2 + 1];
                float ds = q0.x * k0.x + q0.y * k0.y + q0.z * k0.z + q0.w * k0.w
                         + q1.x * k1.x + q1.y * k1.y + q1.z * k1.z + q1.w * k1.w;
                ds += __shfl_xor_sync(FULL, ds, 1);
                ds += __shfl_xor_sync(FULL, ds, 2);
                l = ds + __ldg(&bias[(size_t)e * HEADS + h]);
            }
            float a = __expf(l - mh);
            ssum += a;
            const float4* vp = (const float4*)(v + (size_t)sn * FEAT);
            float4 v0 = vp[lane * 2], v1 = vp[lane * 2 + 1];
            acc[0] = fmaf(a, v0.x, acc[0]);
            acc[1] = fmaf(a, v0.y, acc[1]);
            acc[2] = fmaf(a, v0.z, acc[2]);
            acc[3] = fmaf(a, v0.w, acc[3]);
            acc[4] = fmaf(a, v1.x, acc[4]);
            acc[5] = fmaf(a, v1.y, acc[5]);
            acc[6] = fmaf(a, v1.z, acc[6]);
            acc[7] = fmaf(a, v1.w, acc[7]);
        }
    }

    float r = (deg > 0) ? (1.0f / ssum) : 0.0f;

    float o[8];
#pragma unroll
    for (int j = 0; j < 8; j++) o[j] = acc[j] * r;
    __nv_bfloat16 hi[8], lo[8];
#pragma unroll
    for (int j = 0; j < 8; j++) {
        hi[j] = __float2bfloat16(o[j]);
        lo[j] = __float2bfloat16(o[j] - __bfloat162float(hi[j]));
    }
    uint4 hv, lv;
    hv.x = ((uint32_t)__bfloat16_as_ushort(hi[1]) << 16) | __bfloat16_as_ushort(hi[0]);
    hv.y = ((uint32_t)__bfloat16_as_ushort(hi[3]) << 16) | __bfloat16_as_ushort(hi[2]);
    hv.z = ((uint32_t)__bfloat16_as_ushort(hi[5]) << 16) | __bfloat16_as_ushort(hi[4]);
    hv.w = ((uint32_t)__bfloat16_as_ushort(hi[7]) << 16) | __bfloat16_as_ushort(hi[6]);
    lv.x = ((uint32_t)__bfloat16_as_ushort(lo[1]) << 16) | __bfloat16_as_ushort(lo[0]);
    lv.y = ((uint32_t)__bfloat16_as_ushort(lo[3]) << 16) | __bfloat16_as_ushort(lo[2]);
    lv.z = ((uint32_t)__bfloat16_as_ushort(lo[5]) << 16) | __bfloat16_as_ushort(lo[4]);
    lv.w = ((uint32_t)__bfloat16_as_ushort(lo[7]) << 16) | __bfloat16_as_ushort(lo[6]);
    *(uint4*)(acc2 + (size_t)d * 512 + lane * 8)       = hv;
    *(uint4*)(acc2 + (size_t)d * 512 + 256 + lane * 8) = lv;
}

// ---------------- launch ----------------
extern "C" void kernel_launch(void* const* d_in, const int* in_sizes, int n_in,
                              void* d_out, int out_size) {
    const float* nfeat = (const float*)d_in[0];
    const float* attn_bias = (const float*)d_in[1];
    const float* Wq = (const float*)d_in[2];
    const float* Wk = (const float*)d_in[3];
    const float* Wv = (const float*)d_in[4];
    const float* Wo = (const float*)d_in[5];
    const int* src = (const int*)d_in[6];
    const int* dst = (const int*)d_in[7];
    float* out = (float*)d_out;

    int N = in_sizes[0] / FEAT;
    int E = in_sizes[6];

    float *q, *k, *v;
    __nv_bfloat16 *a2, *acc2, *w2;
    int *cnt, *incl, *off, *cur, *eid, *bsum;
    cudaGetSymbolAddress((void**)&q, g_q);
    cudaGetSymbolAddress((void**)&k, g_k);
    cudaGetSymbolAddress((void**)&v, g_v);
    cudaGetSymbolAddress((void**)&a2, g_a2);
    cudaGetSymbolAddress((void**)&acc2, g_acc2);
    cudaGetSymbolAddress((void**)&w2, g_w2);
    cudaGetSymbolAddress((void**)&cnt, g_cnt);
    cudaGetSymbolAddress((void**)&incl, g_incl);
    cudaGetSymbolAddress((void**)&off, g_off);
    cudaGetSymbolAddress((void**)&cur, g_cur);
    cudaGetSymbolAddress((void**)&eid, g_eid);
    cudaGetSymbolAddress((void**)&bsum, g_bsum);

    cudaFuncSetAttribute(gemm_mma_kernel, cudaFuncAttributeMaxDynamicSharedMemorySize, GSMEM_BYTES);

    // one-time stream/event setup (resource creation only; no device memory)
    static cudaStream_t s_sort = nullptr;
    static cudaEvent_t ev_fork = nullptr, ev_join = nullptr;
    if (!s_sort) {
        cudaStreamCreateWithFlags(&s_sort, cudaStreamNonBlocking);
        cudaEventCreateWithFlags(&ev_fork, cudaEventDisableTiming);
        cudaEventCreateWithFlags(&ev_join, cudaEventDisableTiming);
    }

    // ---- fork: edge counting sort on side stream ----
    cudaEventRecord(ev_fork, 0);
    cudaStreamWaitEvent(s_sort, ev_fork, 0);
    int nb1024 = (N + 1023) / 1024;
    zero_cnt_kernel<<<(N + 255) / 256, 256, 0, s_sort>>>(cnt, N);
    hist_kernel<<<(E + 255) / 256, 256, 0, s_sort>>>(dst, cnt, E);
    scan1_kernel<<<nb1024, 1024, 0, s_sort>>>(cnt, incl, bsum, N);
    scan2_kernel<<<1, 128, 0, s_sort>>>(bsum, nb1024);
    scan3_kernel<<<(N + 255) / 256, 256, 0, s_sort>>>(incl, bsum, cnt, off, cur, N);
    scatter_kernel<<<(E + 255) / 256, 256, 0, s_sort>>>(dst, cur, eid, E);
    cudaEventRecord(ev_join, s_sort);

    // ---- main stream: conversions + projections ----
    int cblocks = (N * 64 + 255) / 256;
    conv_split_kernel<<<cblocks, 256>>>(nfeat, a2, N);
    dim3 wgrid((256 * 768 + 255) / 256, 4);
    conv_w_kernel<<<wgrid, 256>>>(Wq, Wk, Wv, Wo, w2);

    dim3 ggrid(2, (N + 127) / 128);
    const float invScaling = 5.656854249492381f;  // sqrt(HEAD_DIM): reference DIVIDES q by scaling
    gemm_mma_kernel<<<ggrid, 256, GSMEM_BYTES>>>(a2, w2 + 0 * (size_t)256 * 768, q, N, invScaling);
    gemm_mma_kernel<<<ggrid, 256, GSMEM_BYTES>>>(a2, w2 + 1 * (size_t)256 * 768, k, N, 1.0f);
    gemm_mma_kernel<<<ggrid, 256, GSMEM_BYTES>>>(a2, w2 + 2 * (size_t)256 * 768, v, N, 1.0f);

    // ---- join sort before edge kernel ----
    cudaStreamWaitEvent(0, ev_join, 0);

    // ---- fused edge softmax + aggregate ----
    int fblocks = (N + 7) / 8;
    edge_fused_kernel<<<fblocks, 256>>>(q, k, v, attn_bias, src, off, eid, acc2, N);

    // ---- final projection ----
    gemm_mma_kernel<<<ggrid, 256, GSMEM_BYTES>>>(acc2, w2 + 3 * (size_t)256 * 768, out, N, 1.0f);
}